// round 7
// baseline (speedup 1.0000x reference)
#include <cuda_runtime.h>

#define S      256
#define C      5
#define SC     (S * C)          // 1280 floats per image row
#define B      64
#define SPLIT  8
#define TX     32
#define TY     16
#define PITCH_E 173             // k-even in-smem pitch (<=172 floats/row), odd
#define PITCH_O 93              // k-odd  in-smem pitch (<=92 floats/row), odd
#define IN_SZ   3168            // >= max(18*173, 34*93)
#define PITCHW  164             // out-smem pitch (160 data floats), multiple of 4 for LDS.128
#define GRAYW  (0.2989f + 0.5870f + 0.1140f)

// Per-(image,slab,channel) partial weighted sums. No device allocation allowed.
__device__ float g_part[B * SPLIT * C];

__device__ __forceinline__ void get_params(int b,
                                           const float* __restrict__ off_frac,
                                           const int* __restrict__ crop_size,
                                           const int* __restrict__ do_crop,
                                           bool& dc, float& scale, float& off0, float& off1) {
    dc = do_crop[b] != 0;
    float size_f = dc ? (float)crop_size[b] : (float)S;
    scale = size_f / (float)S;
    float span = (float)S - size_f + 1.0f;
    off0 = dc ? floorf(off_frac[2 * b + 0] * span) : 0.0f;
    off1 = dc ? floorf(off_frac[2 * b + 1] * span) : 0.0f;
}

__device__ __forceinline__ void inv_map(int k, bool fl, int y, int x, int& ry, int& rx) {
    switch (k) {
        case 0:  ry = y;         rx = x;         break;
        case 1:  ry = x;         rx = S - 1 - y; break;
        case 2:  ry = S - 1 - y; rx = S - 1 - x; break;
        default: ry = S - 1 - x; rx = y;         break;
    }
    if (fl) rx = S - 1 - rx;
}

// ---------------------------------------------------------------------------
// K1: per-(b,slab,c) partial weighted mean of the resampled image.
// mean = (1/S^2) * sum_{i,j} img[i,j,c] * W0[i] * W1[j]   (near LTS floor)
// ---------------------------------------------------------------------------
__global__ __launch_bounds__(256) void mean_kernel(
    const float* __restrict__ img,
    const float* __restrict__ off_frac,
    const int* __restrict__ crop_size,
    const int* __restrict__ do_crop)
{
    __shared__ float W0[S];
    __shared__ float W1[S];
    __shared__ float red[8][C];

    const int b = blockIdx.x;
    const int slab = blockIdx.y;
    const int t = threadIdx.x;

    bool dc; float scale, off0, off1;
    get_params(b, off_frac, crop_size, do_crop, dc, scale, off0, off1);

    W0[t] = 0.0f;
    W1[t] = 0.0f;
    __syncthreads();

    {
        float base = ((float)t + 0.5f) * scale - 0.5f;

        float c0 = base + off0;
        float f0 = floorf(c0);
        int  i0 = min(max((int)f0, 0), S - 1);
        int  i1 = min(max((int)f0 + 1, 0), S - 1);
        float fy = c0 - f0;
        atomicAdd(&W0[i0], 1.0f - fy);
        atomicAdd(&W0[i1], fy);

        float c1 = base + off1;
        float f1 = floorf(c1);
        int  j0 = min(max((int)f1, 0), S - 1);
        int  j1 = min(max((int)f1 + 1, 0), S - 1);
        float fx = c1 - f1;
        atomicAdd(&W1[j0], 1.0f - fx);
        atomicAdd(&W1[j1], fx);
    }
    __syncthreads();

    const int g = t & 63;          // pixel group (4 px)
    const int r = t >> 6;          // row lane 0..3
    const int px0 = g * 4;
    float w1v0 = W1[px0], w1v1 = W1[px0 + 1], w1v2 = W1[px0 + 2], w1v3 = W1[px0 + 3];

    float acc[C] = {0.f, 0.f, 0.f, 0.f, 0.f};
    const int rows = S / SPLIT;
    const int row0 = slab * rows;
    const float* base = img + (size_t)b * S * S * C;

    for (int it = 0; it < rows / 4; it++) {
        const int i = row0 + r + it * 4;
        const float w0 = W0[i];
        if (w0 == 0.0f) continue;
        const float4* p4 = (const float4*)(base + (size_t)i * SC + px0 * C);
        float4 v0 = p4[0], v1 = p4[1], v2 = p4[2], v3 = p4[3], v4 = p4[4];
        float ww0 = w0 * w1v0, ww1 = w0 * w1v1, ww2 = w0 * w1v2, ww3 = w0 * w1v3;
        acc[0] += v0.x * ww0; acc[1] += v0.y * ww0; acc[2] += v0.z * ww0; acc[3] += v0.w * ww0;
        acc[4] += v1.x * ww0;
        acc[0] += v1.y * ww1; acc[1] += v1.z * ww1; acc[2] += v1.w * ww1;
        acc[3] += v2.x * ww1; acc[4] += v2.y * ww1;
        acc[0] += v2.z * ww2; acc[1] += v2.w * ww2; acc[2] += v3.x * ww2;
        acc[3] += v3.y * ww2; acc[4] += v3.z * ww2;
        acc[0] += v3.w * ww3; acc[1] += v4.x * ww3; acc[2] += v4.y * ww3;
        acc[3] += v4.z * ww3; acc[4] += v4.w * ww3;
    }

#pragma unroll
    for (int c = 0; c < C; c++) {
        float v = acc[c];
#pragma unroll
        for (int o = 16; o > 0; o >>= 1)
            v += __shfl_down_sync(0xffffffffu, v, o);
        if ((t & 31) == 0) red[t >> 5][c] = v;
    }
    __syncthreads();

    if (t < C) {
        float s = 0.f;
#pragma unroll
        for (int w = 0; w < 8; w++) s += red[w][t];
        g_part[(b * SPLIT + slab) * C + t] = s;
    }
}

// ---------------------------------------------------------------------------
// K2: smem-bounced gather so ALL gmem traffic is float4.
//  Phase1: LDG.128 source rect -> in-smem (odd pitch, scalar STS).
//  Phase2: conflict-free LDS gather + fused epilogue -> out-smem (stride 5).
//  Phase3: LDS.128 out-smem -> STG.128 (__stcs) gmem.
// Block = 32x16 output tile; grid (8, 16, B); 256 threads, 2 px/thread.
// ---------------------------------------------------------------------------
__global__ __launch_bounds__(256) void aug_kernel(
    const float* __restrict__ img,
    const float* __restrict__ off_frac,
    const float* __restrict__ bright,
    const float* __restrict__ contrast,
    const int* __restrict__ crop_size,
    const int* __restrict__ do_crop,
    const int* __restrict__ flip,
    const int* __restrict__ rot_k,
    float* __restrict__ out)
{
    __shared__ float IN[IN_SZ];
    __shared__ float OUT[TY * PITCHW];
    __shared__ float Ash[C], Dsh[C];

    const int b  = blockIdx.z;
    const int x0 = blockIdx.x * TX;
    const int y0 = blockIdx.y * TY;
    const int t  = threadIdx.x;

    bool dc; float scale, off0, off1;
    get_params(b, off_frac, crop_size, do_crop, dc, scale, off0, off1);
    const int k = rot_k[b] & 3;
    const bool fl = flip[b] != 0;
    const int pitch = (k & 1) ? PITCH_O : PITCH_E;

    // Source footprint rect from the 4 tile corners (per-axis monotone map).
    int ry_min = S, ry_max = 0, rx_min = S, rx_max = 0;
#pragma unroll
    for (int cn = 0; cn < 4; cn++) {
        int yy = (cn & 1) ? (y0 + TY - 1) : y0;
        int xx = (cn & 2) ? (x0 + TX - 1) : x0;
        int ry, rx;
        inv_map(k, fl, yy, xx, ry, rx);
        ry_min = min(ry_min, ry); ry_max = max(ry_max, ry);
        rx_min = min(rx_min, rx); rx_max = max(rx_max, rx);
    }
    const float cy_min = ((float)ry_min + 0.5f) * scale - 0.5f + off0;
    const float cy_max = ((float)ry_max + 0.5f) * scale - 0.5f + off0;
    const float cx_min = ((float)rx_min + 0.5f) * scale - 0.5f + off1;
    const float cx_max = ((float)rx_max + 0.5f) * scale - 0.5f + off1;
    const int i_min = min(max((int)floorf(cy_min), 0), S - 1);
    const int i_max = min(max((int)floorf(cy_max) + 1, 0), S - 1);
    const int j_min = min(max((int)floorf(cx_min), 0), S - 1);
    const int j_max = min(max((int)floorf(cx_max) + 1, 0), S - 1);
    const int srcH = i_max - i_min + 1;

    const int f_lo = j_min * C;
    const int f_hi = j_max * C + C;
    const int g_start = f_lo & ~3;
    const int width_f = ((f_hi + 3) & ~3) - g_start;

    if (t < C) {
        const float inv_area = 1.0f / (float)(S * S);
        float s = 0.f;
#pragma unroll
        for (int p = 0; p < SPLIT; p++) s += g_part[(b * SPLIT + p) * C + t];
        float m = s * inv_area;
        float cc = contrast[b * C + t];
        Ash[t] = cc * GRAYW;
        Dsh[t] = (m * (1.0f - cc) + bright[b * C + t]) * GRAYW;
    }

    // Phase 1: vectorized coalesced rect load.
    {
        const int wid = t >> 5, lane = t & 31;
        const float* baseg = img + (size_t)b * S * SC + (size_t)i_min * SC + g_start;
        for (int r = wid; r < srcH; r += 8) {
            const float* grow = baseg + (size_t)r * SC;
            float* srow = IN + r * pitch;
            for (int e4 = lane * 4; e4 < width_f; e4 += 128) {
                float4 v = *(const float4*)(grow + e4);
                srow[e4]     = v.x;
                srow[e4 + 1] = v.y;
                srow[e4 + 2] = v.z;
                srow[e4 + 3] = v.w;
            }
        }
    }
    __syncthreads();

    // Phase 2: gather + fused epilogue into out-smem.
#pragma unroll
    for (int q = 0; q < 2; q++) {
        const int p  = t + q * 256;
        const int py = p >> 5;
        const int px = p & 31;
        const int y = y0 + py, x = x0 + px;
        int ry, rx;
        inv_map(k, fl, y, x, ry, rx);

        float* o = OUT + py * PITCHW + px * C;

        if (!dc) {
            const float* src = IN + (ry - i_min) * pitch + (rx * C - g_start);
#pragma unroll
            for (int c = 0; c < C; c++)
                o[c] = src[c] * Ash[c] + Dsh[c];
        } else {
            const float cy = ((float)ry + 0.5f) * scale - 0.5f + off0;
            const float cx = ((float)rx + 0.5f) * scale - 0.5f + off1;
            const float fyf = floorf(cy), fxf = floorf(cx);
            const int i0 = min(max((int)fyf, 0), S - 1);
            const int i1 = min(max((int)fyf + 1, 0), S - 1);
            const int j0 = min(max((int)fxf, 0), S - 1);
            const int j1 = min(max((int)fxf + 1, 0), S - 1);
            const float ty = cy - fyf;
            const float tx = cx - fxf;

            const float* r0 = IN + (i0 - i_min) * pitch;
            const float* r1 = IN + (i1 - i_min) * pitch;
            const int c0 = j0 * C - g_start;
            const int c1 = j1 * C - g_start;
#pragma unroll
            for (int c = 0; c < C; c++) {
                float p00 = r0[c0 + c], p01 = r0[c1 + c];
                float p10 = r1[c0 + c], p11 = r1[c1 + c];
                float a  = p00 + (p10 - p00) * ty;
                float bb = p01 + (p11 - p01) * ty;
                float v  = a + (bb - a) * tx;
                o[c] = v * Ash[c] + Dsh[c];
            }
        }
    }
    __syncthreads();

    // Phase 3: vectorized writeback (evict-first stores; output never re-read).
    {
        float* outbase = out + (((size_t)b * S + y0) * S + x0) * C;
        for (int j = t; j < TY * (TX * C / 4); j += 256) {   // 640 float4s
            const int row  = j / 40;
            const int col4 = j - row * 40;
            float4 v = *(const float4*)(OUT + row * PITCHW + col4 * 4);
            __stcs((float4*)(outbase + (size_t)row * SC + col4 * 4), v);
        }
    }
}

extern "C" void kernel_launch(void* const* d_in, const int* in_sizes, int n_in,
                              void* d_out, int out_size) {
    const float* crops     = (const float*)d_in[0];
    const float* off_frac  = (const float*)d_in[1];
    const float* bright    = (const float*)d_in[2];
    const float* contrast  = (const float*)d_in[3];
    const int*   crop_size = (const int*)d_in[4];
    const int*   do_crop   = (const int*)d_in[5];
    const int*   flip      = (const int*)d_in[6];
    const int*   rot_k     = (const int*)d_in[7];
    float*       out       = (float*)d_out;

    mean_kernel<<<dim3(B, SPLIT), 256>>>(crops, off_frac, crop_size, do_crop);
    aug_kernel<<<dim3(S / TX, S / TY, B), 256>>>(crops, off_frac, bright, contrast,
                                                 crop_size, do_crop, flip, rot_k, out);
}

// round 8
// speedup vs baseline: 1.2316x; 1.2316x over previous
#include <cuda_runtime.h>

#define S      256
#define C      5
#define SC     (S * C)          // 1280 floats per image row
#define B      64
#define SPLIT  8
#define TX     32
#define TY     16
#define PITCH_E 176             // k-even in-smem pitch, multiple of 4 -> STS.128
#define PITCH_O 93              // k-odd  in-smem pitch, odd -> conflict-free row-stride gather
#define IN_SZ   3168            // >= max(18*176, 33*93+92)
#define PITCHW  164             // out-smem pitch (160 data), multiple of 4 for LDS.128
#define GRAYW  (0.2989f + 0.5870f + 0.1140f)

// Per-(image,slab,channel) partial weighted sums. No device allocation allowed.
__device__ float g_part[B * SPLIT * C];

__device__ __forceinline__ void get_params(int b,
                                           const float* __restrict__ off_frac,
                                           const int* __restrict__ crop_size,
                                           const int* __restrict__ do_crop,
                                           bool& dc, float& scale, float& off0, float& off1) {
    dc = do_crop[b] != 0;
    float size_f = dc ? (float)crop_size[b] : (float)S;
    scale = size_f / (float)S;
    float span = (float)S - size_f + 1.0f;
    off0 = dc ? floorf(off_frac[2 * b + 0] * span) : 0.0f;
    off1 = dc ? floorf(off_frac[2 * b + 1] * span) : 0.0f;
}

__device__ __forceinline__ void inv_map(int k, bool fl, int y, int x, int& ry, int& rx) {
    switch (k) {
        case 0:  ry = y;         rx = x;         break;
        case 1:  ry = x;         rx = S - 1 - y; break;
        case 2:  ry = S - 1 - y; rx = S - 1 - x; break;
        default: ry = S - 1 - x; rx = y;         break;
    }
    if (fl) rx = S - 1 - rx;
}

// ---------------------------------------------------------------------------
// K1: per-(b,slab,c) partial weighted mean of the resampled image (~LTS cap).
// ---------------------------------------------------------------------------
__global__ __launch_bounds__(256) void mean_kernel(
    const float* __restrict__ img,
    const float* __restrict__ off_frac,
    const int* __restrict__ crop_size,
    const int* __restrict__ do_crop)
{
    __shared__ float W0[S];
    __shared__ float W1[S];
    __shared__ float red[8][C];

    const int b = blockIdx.x;
    const int slab = blockIdx.y;
    const int t = threadIdx.x;

    bool dc; float scale, off0, off1;
    get_params(b, off_frac, crop_size, do_crop, dc, scale, off0, off1);

    W0[t] = 0.0f;
    W1[t] = 0.0f;
    __syncthreads();

    {
        float base = ((float)t + 0.5f) * scale - 0.5f;

        float c0 = base + off0;
        float f0 = floorf(c0);
        int  i0 = min(max((int)f0, 0), S - 1);
        int  i1 = min(max((int)f0 + 1, 0), S - 1);
        float fy = c0 - f0;
        atomicAdd(&W0[i0], 1.0f - fy);
        atomicAdd(&W0[i1], fy);

        float c1 = base + off1;
        float f1 = floorf(c1);
        int  j0 = min(max((int)f1, 0), S - 1);
        int  j1 = min(max((int)f1 + 1, 0), S - 1);
        float fx = c1 - f1;
        atomicAdd(&W1[j0], 1.0f - fx);
        atomicAdd(&W1[j1], fx);
    }
    __syncthreads();

    const int g = t & 63;          // pixel group (4 px)
    const int r = t >> 6;          // row lane 0..3
    const int px0 = g * 4;
    float w1v0 = W1[px0], w1v1 = W1[px0 + 1], w1v2 = W1[px0 + 2], w1v3 = W1[px0 + 3];

    float acc[C] = {0.f, 0.f, 0.f, 0.f, 0.f};
    const int rows = S / SPLIT;
    const int row0 = slab * rows;
    const float* base = img + (size_t)b * S * S * C;

    for (int it = 0; it < rows / 4; it++) {
        const int i = row0 + r + it * 4;
        const float w0 = W0[i];
        if (w0 == 0.0f) continue;
        const float4* p4 = (const float4*)(base + (size_t)i * SC + px0 * C);
        float4 v0 = p4[0], v1 = p4[1], v2 = p4[2], v3 = p4[3], v4 = p4[4];
        float ww0 = w0 * w1v0, ww1 = w0 * w1v1, ww2 = w0 * w1v2, ww3 = w0 * w1v3;
        acc[0] += v0.x * ww0; acc[1] += v0.y * ww0; acc[2] += v0.z * ww0; acc[3] += v0.w * ww0;
        acc[4] += v1.x * ww0;
        acc[0] += v1.y * ww1; acc[1] += v1.z * ww1; acc[2] += v1.w * ww1;
        acc[3] += v2.x * ww1; acc[4] += v2.y * ww1;
        acc[0] += v2.z * ww2; acc[1] += v2.w * ww2; acc[2] += v3.x * ww2;
        acc[3] += v3.y * ww2; acc[4] += v3.z * ww2;
        acc[0] += v3.w * ww3; acc[1] += v4.x * ww3; acc[2] += v4.y * ww3;
        acc[3] += v4.z * ww3; acc[4] += v4.w * ww3;
    }

#pragma unroll
    for (int c = 0; c < C; c++) {
        float v = acc[c];
#pragma unroll
        for (int o = 16; o > 0; o >>= 1)
            v += __shfl_down_sync(0xffffffffu, v, o);
        if ((t & 31) == 0) red[t >> 5][c] = v;
    }
    __syncthreads();

    if (t < C) {
        float s = 0.f;
#pragma unroll
        for (int w = 0; w < 8; w++) s += red[w][t];
        g_part[(b * SPLIT + slab) * C + t] = s;
    }
}

// ---------------------------------------------------------------------------
// K2: 3-phase smem-bounced gather, instruction-slimmed.
//  Tables: per-axis bilinear params precomputed once per block (48 threads).
//  Phase1: LDG.128 rect -> smem (STS.128 for k-even).
//  Phase2: table-driven gather + fused epilogue -> out-smem.
//  Phase3: LDS.128 -> STG.128 (__stcs).
// Block = 32x16 output tile; grid (8, 16, B); 256 threads, 2 px/thread.
// ---------------------------------------------------------------------------
__global__ __launch_bounds__(256) void aug_kernel(
    const float* __restrict__ img,
    const float* __restrict__ off_frac,
    const float* __restrict__ bright,
    const float* __restrict__ contrast,
    const int* __restrict__ crop_size,
    const int* __restrict__ do_crop,
    const int* __restrict__ flip,
    const int* __restrict__ rot_k,
    float* __restrict__ out)
{
    __shared__ float IN[IN_SZ];
    __shared__ float OUT[TY * PITCHW];
    __shared__ float Ash[C], Dsh[C];
    __shared__ int   RI0[TX], RI1[TX];      // row offsets, pre-multiplied by pitch
    __shared__ float RF[TX];
    __shared__ int   CI0[TX], CI1[TX];      // col offsets (j*5 - g_start)
    __shared__ float CF[TX];

    const int b  = blockIdx.z;
    const int x0 = blockIdx.x * TX;
    const int y0 = blockIdx.y * TY;
    const int t  = threadIdx.x;

    bool dc; float scale, off0, off1;
    get_params(b, off_frac, crop_size, do_crop, dc, scale, off0, off1);
    const int k = rot_k[b] & 3;
    const bool fl = flip[b] != 0;
    const int kodd = k & 1;
    const int pitch = kodd ? PITCH_O : PITCH_E;

    // Source footprint rect from the 4 tile corners.
    int ry_min = S, ry_max = 0, rx_min = S, rx_max = 0;
#pragma unroll
    for (int cn = 0; cn < 4; cn++) {
        int yy = (cn & 1) ? (y0 + TY - 1) : y0;
        int xx = (cn & 2) ? (x0 + TX - 1) : x0;
        int ry, rx;
        inv_map(k, fl, yy, xx, ry, rx);
        ry_min = min(ry_min, ry); ry_max = max(ry_max, ry);
        rx_min = min(rx_min, rx); rx_max = max(rx_max, rx);
    }
    const float cy_min = ((float)ry_min + 0.5f) * scale - 0.5f + off0;
    const float cy_max = ((float)ry_max + 0.5f) * scale - 0.5f + off0;
    const float cx_min = ((float)rx_min + 0.5f) * scale - 0.5f + off1;
    const float cx_max = ((float)rx_max + 0.5f) * scale - 0.5f + off1;
    const int i_min = min(max((int)floorf(cy_min), 0), S - 1);
    const int j_min = min(max((int)floorf(cx_min), 0), S - 1);
    const int i_max = min(max((int)floorf(cy_max) + 1, 0), S - 1);
    const int srcH = i_max - i_min + 1;

    const int f_lo = j_min * C;
    const int g_start = f_lo & ~3;
    int j_maxc = min(max((int)floorf(cx_max) + 1, 0), S - 1);
    const int width_f = (((j_maxc * C + C) + 3) & ~3) - g_start;

    // ---- per-axis bilinear tables ----
    if (t < TY) {                       // from output y
        int ry, rx;
        inv_map(k, fl, y0 + t, x0, ry, rx);
        if (!kodd) {                    // y -> source row
            float cy = ((float)ry + 0.5f) * scale - 0.5f + off0;
            float f = floorf(cy);
            RI0[t] = (min(max((int)f, 0), S - 1) - i_min) * pitch;
            RI1[t] = (min(max((int)f + 1, 0), S - 1) - i_min) * pitch;
            RF[t] = cy - f;
        } else {                        // y -> source col
            float cx = ((float)rx + 0.5f) * scale - 0.5f + off1;
            float f = floorf(cx);
            CI0[t] = min(max((int)f, 0), S - 1) * C - g_start;
            CI1[t] = min(max((int)f + 1, 0), S - 1) * C - g_start;
            CF[t] = cx - f;
        }
    }
    if (t >= 64 && t < 64 + TX) {       // from output x
        int i = t - 64;
        int ry, rx;
        inv_map(k, fl, y0, x0 + i, ry, rx);
        if (!kodd) {                    // x -> source col
            float cx = ((float)rx + 0.5f) * scale - 0.5f + off1;
            float f = floorf(cx);
            CI0[i] = min(max((int)f, 0), S - 1) * C - g_start;
            CI1[i] = min(max((int)f + 1, 0), S - 1) * C - g_start;
            CF[i] = cx - f;
        } else {                        // x -> source row
            float cy = ((float)ry + 0.5f) * scale - 0.5f + off0;
            float f = floorf(cy);
            RI0[i] = (min(max((int)f, 0), S - 1) - i_min) * pitch;
            RI1[i] = (min(max((int)f + 1, 0), S - 1) - i_min) * pitch;
            RF[i] = cy - f;
        }
    }
    if (t >= 32 && t < 32 + C) {        // fused epilogue params: o = v*A + D
        int c = t - 32;
        const float inv_area = 1.0f / (float)(S * S);
        float s = 0.f;
#pragma unroll
        for (int p = 0; p < SPLIT; p++) s += g_part[(b * SPLIT + p) * C + c];
        float m = s * inv_area;
        float cc = contrast[b * C + c];
        Ash[c] = cc * GRAYW;
        Dsh[c] = (m * (1.0f - cc) + bright[b * C + c]) * GRAYW;
    }

    // ---- Phase 1: coalesced rect load ----
    {
        const int wid = t >> 5, lane = t & 31;
        const float* baseg = img + (size_t)b * S * SC + (size_t)i_min * SC + g_start;
        if (!kodd) {
            for (int r = wid; r < srcH; r += 8) {
                const float* grow = baseg + (size_t)r * SC;
                float* srow = IN + r * PITCH_E;
                for (int e4 = lane * 4; e4 < width_f; e4 += 128)
                    *(float4*)(srow + e4) = *(const float4*)(grow + e4);
            }
        } else {
            for (int r = wid; r < srcH; r += 8) {
                const float* grow = baseg + (size_t)r * SC;
                float* srow = IN + r * PITCH_O;
                for (int e4 = lane * 4; e4 < width_f; e4 += 128) {
                    float4 v = *(const float4*)(grow + e4);
                    srow[e4]     = v.x;
                    srow[e4 + 1] = v.y;
                    srow[e4 + 2] = v.z;
                    srow[e4 + 3] = v.w;
                }
            }
        }
    }
    __syncthreads();

    // ---- Phase 2: table-driven gather + epilogue into out-smem ----
#pragma unroll
    for (int q = 0; q < 2; q++) {
        const int p  = t + q * 256;
        const int py = p >> 5;
        const int px = p & 31;
        const int ri = kodd ? px : py;
        const int ci = kodd ? py : px;

        float* o = OUT + py * PITCHW + px * C;
        const int r0 = RI0[ri];
        const int c0 = CI0[ci];

        if (!dc) {
            const float* s = IN + r0 + c0;
#pragma unroll
            for (int c = 0; c < C; c++)
                o[c] = s[c] * Ash[c] + Dsh[c];
        } else {
            const int r1 = RI1[ri];
            const int c1 = CI1[ci];
            const float ty = RF[ri];
            const float tx = CF[ci];
            const float* a0 = IN + r0;
            const float* a1 = IN + r1;
#pragma unroll
            for (int c = 0; c < C; c++) {
                float p00 = a0[c0 + c], p01 = a0[c1 + c];
                float p10 = a1[c0 + c], p11 = a1[c1 + c];
                float a  = p00 + (p10 - p00) * ty;
                float bb = p01 + (p11 - p01) * ty;
                float v  = a + (bb - a) * tx;
                o[c] = v * Ash[c] + Dsh[c];
            }
        }
    }
    __syncthreads();

    // ---- Phase 3: vectorized writeback (evict-first) ----
    {
        float* outbase = out + (((size_t)b * S + y0) * S + x0) * C;
        for (int j = t; j < TY * (TX * C / 4); j += 256) {   // 640 float4s
            const int row  = j / 40;
            const int col4 = j - row * 40;
            float4 v = *(const float4*)(OUT + row * PITCHW + col4 * 4);
            __stcs((float4*)(outbase + (size_t)row * SC + col4 * 4), v);
        }
    }
}

extern "C" void kernel_launch(void* const* d_in, const int* in_sizes, int n_in,
                              void* d_out, int out_size) {
    const float* crops     = (const float*)d_in[0];
    const float* off_frac  = (const float*)d_in[1];
    const float* bright    = (const float*)d_in[2];
    const float* contrast  = (const float*)d_in[3];
    const int*   crop_size = (const int*)d_in[4];
    const int*   do_crop   = (const int*)d_in[5];
    const int*   flip      = (const int*)d_in[6];
    const int*   rot_k     = (const int*)d_in[7];
    float*       out       = (float*)d_out;

    mean_kernel<<<dim3(B, SPLIT), 256>>>(crops, off_frac, crop_size, do_crop);
    aug_kernel<<<dim3(S / TX, S / TY, B), 256>>>(crops, off_frac, bright, contrast,
                                                 crop_size, do_crop, flip, rot_k, out);
}